// round 1
// baseline (speedup 1.0000x reference)
#include <cuda_runtime.h>
#include <cuda_bf16.h>
#include <math.h>

#define N_NODES_MAX 100000
#define E_MAX       3200000
#define D_IN        256
#define H1          16
#define H2          32

// Scratch (device globals — no allocation allowed)
__device__ float g_y[N_NODES_MAX * H1];   // x @ W1
__device__ float g_a[N_NODES_MAX * H1];   // spmm accumulator (pre-relu)
__device__ float g_s[N_NODES_MAX];        // s[j] = sum_{e: col==j} val[e]
__device__ float g_t[H1];                 // t = sum_i s[i]*relu(a[i])

// ---------------------------------------------------------------------------
// Zero the accumulators
// ---------------------------------------------------------------------------
__global__ void zero_kernel(int n) {
    int i = blockIdx.x * blockDim.x + threadIdx.x;
    int stride = gridDim.x * blockDim.x;
    for (int j = i; j < n * H1; j += stride) g_a[j] = 0.0f;
    for (int j = i; j < n; j += stride) g_s[j] = 0.0f;
    if (i < H1) g_t[i] = 0.0f;
}

// ---------------------------------------------------------------------------
// y = x @ W1   (N x 256) @ (256 x 16)
// Thread per row; W1 in shared (broadcast reads, float4).
// ---------------------------------------------------------------------------
__global__ void gemm1_kernel(const float* __restrict__ x,
                             const float* __restrict__ W1, int n) {
    __shared__ float4 sW[D_IN * H1 / 4];  // [k][f/4] : 1024 float4 = 16KB
    for (int i = threadIdx.x; i < D_IN * H1 / 4; i += blockDim.x)
        sW[i] = reinterpret_cast<const float4*>(W1)[i];
    __syncthreads();

    int row = blockIdx.x * blockDim.x + threadIdx.x;
    int stride = gridDim.x * blockDim.x;
    for (; row < n; row += stride) {
        const float4* xr = reinterpret_cast<const float4*>(x + (size_t)row * D_IN);
        float4 acc0 = {0.f, 0.f, 0.f, 0.f};
        float4 acc1 = {0.f, 0.f, 0.f, 0.f};
        float4 acc2 = {0.f, 0.f, 0.f, 0.f};
        float4 acc3 = {0.f, 0.f, 0.f, 0.f};
#pragma unroll 8
        for (int k4 = 0; k4 < D_IN / 4; k4++) {
            float4 xv = xr[k4];
#pragma unroll
            for (int kk = 0; kk < 4; kk++) {
                float xs = (kk == 0) ? xv.x : (kk == 1) ? xv.y : (kk == 2) ? xv.z : xv.w;
                int k = 4 * k4 + kk;
                float4 w0 = sW[k * 4 + 0];
                float4 w1 = sW[k * 4 + 1];
                float4 w2 = sW[k * 4 + 2];
                float4 w3 = sW[k * 4 + 3];
                acc0.x += xs * w0.x; acc0.y += xs * w0.y; acc0.z += xs * w0.z; acc0.w += xs * w0.w;
                acc1.x += xs * w1.x; acc1.y += xs * w1.y; acc1.z += xs * w1.z; acc1.w += xs * w1.w;
                acc2.x += xs * w2.x; acc2.y += xs * w2.y; acc2.z += xs * w2.z; acc2.w += xs * w2.w;
                acc3.x += xs * w3.x; acc3.y += xs * w3.y; acc3.z += xs * w3.z; acc3.w += xs * w3.w;
            }
        }
        float4* yr = reinterpret_cast<float4*>(g_y + (size_t)row * H1);
        yr[0] = acc0; yr[1] = acc1; yr[2] = acc2; yr[3] = acc3;
    }
}

// ---------------------------------------------------------------------------
// Edge pass: a[r] += v * y[c]  (16-wide, half-warp per edge, coalesced REDs)
//            s[c] += v
// ---------------------------------------------------------------------------
__global__ void edge_kernel(const int* __restrict__ rows,
                            const int* __restrict__ cols,
                            const float* __restrict__ vals, int e_count) {
    int gid = blockIdx.x * blockDim.x + threadIdx.x;
    int f = gid & (H1 - 1);
    int e = gid >> 4;
    int estride = (gridDim.x * blockDim.x) >> 4;
    for (; e < e_count; e += estride) {
        int r = __ldg(rows + e);
        int c = __ldg(cols + e);
        float v = __ldg(vals + e);
        float yv = g_y[c * H1 + f];
        atomicAdd(&g_a[r * H1 + f], v * yv);   // RED (no return)
        if (f == 0) atomicAdd(&g_s[c], v);
    }
}

// ---------------------------------------------------------------------------
// t[f] = sum_i s[i] * relu(a[i][f])
// ---------------------------------------------------------------------------
__global__ void reduce_kernel(int n) {
    __shared__ float red[256];
    int tid = threadIdx.x;
    int f = tid & (H1 - 1);
    float acc = 0.0f;
    int gid = blockIdx.x * blockDim.x + tid;
    int stride = gridDim.x * blockDim.x;  // multiple of 16
    int total = n * H1;
    for (int idx = gid; idx < total; idx += stride) {
        int i = idx >> 4;
        float av = g_a[idx];
        av = av > 0.0f ? av : 0.0f;
        acc += g_s[i] * av;
    }
    red[tid] = acc;
    __syncthreads();
#pragma unroll
    for (int off = 128; off >= H1; off >>= 1) {
        if (tid < off && off > H1) red[tid] += red[tid + off];
        else if (tid < H1 && off == H1) red[tid] += red[tid + off];
        __syncthreads();
    }
    if (tid < H1) atomicAdd(&g_t[f], red[tid]);
}

// ---------------------------------------------------------------------------
// out = sigmoid( (t @ W2) . w_out + b_out )
// ---------------------------------------------------------------------------
__global__ void final_kernel(const float* __restrict__ W2,
                             const float* __restrict__ w_out,
                             const float* __restrict__ b_out,
                             float* __restrict__ out) {
    int j = threadIdx.x;  // 0..31
    float z = 0.0f;
#pragma unroll
    for (int fi = 0; fi < H1; fi++) z += g_t[fi] * W2[fi * H2 + j];
    float p = z * w_out[j];
#pragma unroll
    for (int o = 16; o > 0; o >>= 1) p += __shfl_xor_sync(0xffffffffu, p, o);
    if (j == 0) out[0] = 1.0f / (1.0f + expf(-(p + b_out[0])));
}

// ---------------------------------------------------------------------------
extern "C" void kernel_launch(void* const* d_in, const int* in_sizes, int n_in,
                              void* d_out, int out_size) {
    const float* x     = (const float*)d_in[0];
    const float* vals  = (const float*)d_in[1];
    const float* W1    = (const float*)d_in[2];
    const float* W2    = (const float*)d_in[3];
    const float* w_out = (const float*)d_in[4];
    const float* b_out = (const float*)d_in[5];
    const int*   rows  = (const int*)d_in[6];
    const int*   cols  = (const int*)d_in[7];

    int n = in_sizes[0] / D_IN;   // 100000
    int e = in_sizes[1];          // 3200000

    zero_kernel<<<2048, 256>>>(n);
    gemm1_kernel<<<(n + 255) / 256, 256>>>(x, W1, n);
    {
        long long work = (long long)e * H1;
        int blocks = (int)((work + 255) / 256);
        edge_kernel<<<blocks, 256>>>(rows, cols, vals, e);
    }
    reduce_kernel<<<1024, 256>>>(n);
    final_kernel<<<1, 32>>>(W2, w_out, b_out, (float*)d_out);
}

// round 2
// speedup vs baseline: 1.7984x; 1.7984x over previous
#include <cuda_runtime.h>
#include <cuda_bf16.h>
#include <math.h>

#define N_NODES_MAX 100000
#define D_IN        256
#define H1          16
#define H2          32

// Scratch (device globals — no allocation allowed)
__device__ __align__(256) float g_y[N_NODES_MAX * H1];   // x @ W1
__device__ __align__(256) float g_a[N_NODES_MAX * H1];   // spmm accumulator (pre-relu)
__device__ __align__(256) float g_s[N_NODES_MAX];        // s[j] = sum_{e: col==j} val[e]
__device__ __align__(256) float g_t[H1];                 // t = sum_i s[i]*relu(a[i])

// ---------------------------------------------------------------------------
// y = x @ W1   (N x 256) @ (256 x 16). Thread per row; W1 in shared.
// Also zeroes g_a row, g_s[row], g_t (fused to kill the zero_kernel launch).
// ---------------------------------------------------------------------------
__global__ void gemm1_kernel(const float* __restrict__ x,
                             const float* __restrict__ W1, int n) {
    __shared__ float4 sW[D_IN * H1 / 4];  // [k][g] : 1024 float4 = 16KB
    for (int i = threadIdx.x; i < D_IN * H1 / 4; i += blockDim.x)
        sW[i] = reinterpret_cast<const float4*>(W1)[i];
    __syncthreads();

    if (blockIdx.x == 0 && threadIdx.x < H1) g_t[threadIdx.x] = 0.0f;

    int row = blockIdx.x * blockDim.x + threadIdx.x;
    int stride = gridDim.x * blockDim.x;
    const float4 z4 = {0.f, 0.f, 0.f, 0.f};
    for (; row < n; row += stride) {
        const float4* xr = reinterpret_cast<const float4*>(x + (size_t)row * D_IN);
        float4 acc0 = z4, acc1 = z4, acc2 = z4, acc3 = z4;
#pragma unroll 8
        for (int k4 = 0; k4 < D_IN / 4; k4++) {
            float4 xv = xr[k4];
#pragma unroll
            for (int kk = 0; kk < 4; kk++) {
                float xs = (kk == 0) ? xv.x : (kk == 1) ? xv.y : (kk == 2) ? xv.z : xv.w;
                int k = 4 * k4 + kk;
                float4 w0 = sW[k * 4 + 0];
                float4 w1 = sW[k * 4 + 1];
                float4 w2 = sW[k * 4 + 2];
                float4 w3 = sW[k * 4 + 3];
                acc0.x += xs * w0.x; acc0.y += xs * w0.y; acc0.z += xs * w0.z; acc0.w += xs * w0.w;
                acc1.x += xs * w1.x; acc1.y += xs * w1.y; acc1.z += xs * w1.z; acc1.w += xs * w1.w;
                acc2.x += xs * w2.x; acc2.y += xs * w2.y; acc2.z += xs * w2.z; acc2.w += xs * w2.w;
                acc3.x += xs * w3.x; acc3.y += xs * w3.y; acc3.z += xs * w3.z; acc3.w += xs * w3.w;
            }
        }
        float4* yr = reinterpret_cast<float4*>(g_y + (size_t)row * H1);
        yr[0] = acc0; yr[1] = acc1; yr[2] = acc2; yr[3] = acc3;
        // fused zeroing for the next stage
        float4* ar = reinterpret_cast<float4*>(g_a + (size_t)row * H1);
        ar[0] = z4; ar[1] = z4; ar[2] = z4; ar[3] = z4;
        g_s[row] = 0.0f;
    }
}

// ---------------------------------------------------------------------------
// Edge pass: a[r] += v * y[c] via red.global.add.v4.f32 (4 lanes per edge)
//            s[c] += v (scalar RED, lane 0 of each quad)
// ---------------------------------------------------------------------------
__global__ void edge_kernel(const int* __restrict__ rows,
                            const int* __restrict__ cols,
                            const float* __restrict__ vals, int e_count) {
    int gid = blockIdx.x * blockDim.x + threadIdx.x;
    int q = gid & 3;           // quarter of the 16-wide feature row
    int e = gid >> 2;
    if (e >= e_count) return;

    int r = __ldg(rows + e);
    int c = __ldg(cols + e);
    float v = __ldg(vals + e);

    const float4 yv = *reinterpret_cast<const float4*>(g_y + (size_t)c * H1 + q * 4);
    float px = v * yv.x, py = v * yv.y, pz = v * yv.z, pw = v * yv.w;
    float* dst = g_a + (size_t)r * H1 + q * 4;
    asm volatile("red.global.add.v4.f32 [%0], {%1, %2, %3, %4};"
                 :: "l"(dst), "f"(px), "f"(py), "f"(pz), "f"(pw) : "memory");
    if (q == 0) atomicAdd(&g_s[c], v);
}

// ---------------------------------------------------------------------------
// t[f] = sum_i s[i] * relu(a[i][f])  — float4 per thread, L2-resident data
// ---------------------------------------------------------------------------
__global__ void reduce_kernel(int n) {
    __shared__ float4 red[256];
    int tid = threadIdx.x;
    int g = tid & 3;  // feature group: covers features [4g, 4g+4)
    float4 acc = {0.f, 0.f, 0.f, 0.f};
    int total = n * 4;
    int stride = gridDim.x * blockDim.x;  // multiple of 4 -> idx&3 invariant
    for (int idx = blockIdx.x * blockDim.x + tid; idx < total; idx += stride) {
        int i = idx >> 2;
        float4 av = *reinterpret_cast<const float4*>(g_a + (size_t)i * H1 + g * 4);
        float s = g_s[i];
        acc.x += s * fmaxf(av.x, 0.f);
        acc.y += s * fmaxf(av.y, 0.f);
        acc.z += s * fmaxf(av.z, 0.f);
        acc.w += s * fmaxf(av.w, 0.f);
    }
    red[tid] = acc;
    __syncthreads();
#pragma unroll
    for (int off = 128; off >= 4; off >>= 1) {
        if (tid < off) {
            float4 o = red[tid + off];
            red[tid].x += o.x; red[tid].y += o.y; red[tid].z += o.z; red[tid].w += o.w;
        }
        __syncthreads();
    }
    if (tid < 4) {
        float4 r4 = red[tid];
        float* dst = g_t + tid * 4;
        asm volatile("red.global.add.v4.f32 [%0], {%1, %2, %3, %4};"
                     :: "l"(dst), "f"(r4.x), "f"(r4.y), "f"(r4.z), "f"(r4.w) : "memory");
    }
}

// ---------------------------------------------------------------------------
// out = sigmoid( (t @ W2) . w_out + b_out )
// ---------------------------------------------------------------------------
__global__ void final_kernel(const float* __restrict__ W2,
                             const float* __restrict__ w_out,
                             const float* __restrict__ b_out,
                             float* __restrict__ out) {
    int j = threadIdx.x;  // 0..31
    float z = 0.0f;
#pragma unroll
    for (int fi = 0; fi < H1; fi++) z += g_t[fi] * W2[fi * H2 + j];
    float p = z * w_out[j];
#pragma unroll
    for (int o = 16; o > 0; o >>= 1) p += __shfl_xor_sync(0xffffffffu, p, o);
    if (j == 0) out[0] = 1.0f / (1.0f + expf(-(p + b_out[0])));
}

// ---------------------------------------------------------------------------
extern "C" void kernel_launch(void* const* d_in, const int* in_sizes, int n_in,
                              void* d_out, int out_size) {
    const float* x     = (const float*)d_in[0];
    const float* vals  = (const float*)d_in[1];
    const float* W1    = (const float*)d_in[2];
    const float* W2    = (const float*)d_in[3];
    const float* w_out = (const float*)d_in[4];
    const float* b_out = (const float*)d_in[5];
    const int*   rows  = (const int*)d_in[6];
    const int*   cols  = (const int*)d_in[7];

    int n = in_sizes[0] / D_IN;   // 100000
    int e = in_sizes[1];          // 3200000

    gemm1_kernel<<<(n + 255) / 256, 256>>>(x, W1, n);
    {
        long long work = (long long)e * 4;
        int blocks = (int)((work + 255) / 256);
        edge_kernel<<<blocks, 256>>>(rows, cols, vals, e);
    }
    reduce_kernel<<<1024, 256>>>(n);
    final_kernel<<<1, 32>>>(W2, w_out, b_out, (float*)d_out);
}